// round 3
// baseline (speedup 1.0000x reference)
#include <cuda_runtime.h>

// CoExCostVolume: cost[b,d,h,w] = sum_c x[b,c,h,w] * y[b,c,h,w-d], zero for w<d.
// B=8, C=96, H=128, W=416, D=49.
//
// One CTA per (b,h) row. cp.async(8B) double-buffered channel chunks (24 ch),
// smem skewed +2 floats per 16 (8B-alignment preserving, bank-spreading),
// LDS.64 operand loads feeding packed fma.rn.f32x2 (7d x 8w tile / thread).

#define B_DIM 8
#define C_DIM 96
#define H_DIM 128
#define W_DIM 416
#define D_DIM 49
#define HW (H_DIM * W_DIM)

#define CC 24
#define NC 4
#define XSTRIDE 468           // >= sidx2(415)+1 = 466, mult of 4
#define YSTRIDE 524           // >= max read sidx2(464)+2 = 524-ish headroom
#define XSZ (CC * XSTRIDE)
#define YSZ (CC * YSTRIDE)
#define BUFSZ (XSZ + YSZ)
#define NTHREADS 384
#define SMEM_BYTES (2 * BUFSZ * 4)

typedef unsigned long long ull;

// skew: +2 floats per 16-float block; keeps 8B alignment of even offsets
__device__ __forceinline__ int sidx2(int p) { return p + ((p >> 4) << 1); }

__device__ __forceinline__ void cp8(float* dst_smem, const float* src) {
    unsigned sdst = (unsigned)__cvta_generic_to_shared(dst_smem);
    asm volatile("cp.async.ca.shared.global [%0], [%1], 8;\n" ::"r"(sdst), "l"(src));
}
__device__ __forceinline__ ull pk(float lo, float hi) {
    ull r; asm("mov.b64 %0, {%1, %2};" : "=l"(r) : "f"(lo), "f"(hi)); return r;
}
__device__ __forceinline__ void fma2(ull& d, ull a, ull b) {
    asm("fma.rn.f32x2 %0, %1, %2, %0;" : "+l"(d) : "l"(a), "l"(b));
}
__device__ __forceinline__ float2 upk(ull p) {
    float2 v; asm("mov.b64 {%0, %1}, %2;" : "=f"(v.x), "=f"(v.y) : "l"(p)); return v;
}

// One channel-chunk of accumulation. SH = parity of the y window base.
template <int SH>
__device__ __forceinline__ void accum_chunk(const float* __restrict__ buf,
                                            int xb, const int* yo,
                                            ull acc[28]) {
    const float* xr = buf + xb;
    const float* yr = buf + XSZ;
#pragma unroll 2
    for (int c = 0; c < CC; c++) {
        float2 xp[4];
#pragma unroll
        for (int j = 0; j < 4; j++)
            xp[j] = *reinterpret_cast<const float2*>(xr + 2 * j);
        float2 hv[8];
#pragma unroll
        for (int k = 0; k < 8; k++)
            hv[k] = *reinterpret_cast<const float2*>(yr + yo[k]);

        ull px[4];
#pragma unroll
        for (int j = 0; j < 4; j++) px[j] = pk(xp[j].x, xp[j].y);

        ull py[13];
#pragma unroll
        for (int t = 0; t < 13; t++) {
            const int a = t + SH;                 // float offset in window
            if ((a & 1) == 0)
                py[t] = pk(hv[a >> 1].x, hv[a >> 1].y);
            else
                py[t] = pk(hv[a >> 1].y, hv[(a >> 1) + 1].x);
        }

#pragma unroll
        for (int i = 0; i < 7; i++)
#pragma unroll
            for (int j = 0; j < 4; j++)
                fma2(acc[i * 4 + j], px[j], py[2 * j + 6 - i]);

        xr += XSTRIDE;
        yr += YSTRIDE;
    }
}

__global__ void __launch_bounds__(NTHREADS, 1)
coex_cost_kernel(const float* __restrict__ x,
                 const float* __restrict__ y,
                 float* __restrict__ out) {
    extern __shared__ float sm[];

    const int bid = blockIdx.x;
    const int b = bid >> 7;
    const int h = bid & 127;
    const int tid = threadIdx.x;

    const int dth = tid / 52;        // 0..7 (7 = staging-only)
    const int wth = tid - dth * 52;  // 0..51
    const bool active = (dth < 7);
    const int d0 = dth * 7;
    const int w0 = wth * 8;

    // ---- zero y left-pad region once (both buffers): skewed coords [0,52) ----
    for (int i = tid; i < 2 * CC * 52; i += NTHREADS) {
        int br = i / 52;
        int p = i - br * 52;
        int buf = br / CC;
        int c = br - buf * CC;
        sm[buf * BUFSZ + XSZ + c * YSTRIDE + p] = 0.0f;
    }

    // ---- per-thread window offsets ----
    const int yb = w0 - (active ? d0 : 0) + 42;  // window base (padded coords)
    const int sh = yb & 1;
    const int qa = yb - sh;                       // even-aligned base
    int yo[8];
#pragma unroll
    for (int k = 0; k < 8; k++) yo[k] = sidx2(qa + 2 * k);
    const int xb = sidx2(w0);

    ull acc[28];
#pragma unroll
    for (int i = 0; i < 28; i++) acc[i] = 0ull;

    const long gbase = ((long)(b * C_DIM) * H_DIM + h) * W_DIM;

    // ---- staging: 8-byte cp.async, 13 float2 per array per thread ----
    auto stage = [&](int k) {
        const float* xg = x + gbase + (long)k * CC * HW;
        const float* yg = y + gbase + (long)k * CC * HW;
        float* xs = sm + (k & 1) * BUFSZ;
        float* ys = xs + XSZ;
#pragma unroll 2
        for (int it = 0; it < (CC * W_DIM / 2) / NTHREADS; it++) {
            int idx = tid + it * NTHREADS;       // float2 index, < 4992
            int c = idx / 208;
            int w = (idx - c * 208) * 2;
            cp8(xs + c * XSTRIDE + sidx2(w), xg + (long)c * HW + w);
            cp8(ys + c * YSTRIDE + sidx2(48 + w), yg + (long)c * HW + w);
        }
    };

    stage(0);
    asm volatile("cp.async.commit_group;\n");

    for (int k = 0; k < NC; k++) {
        if (k + 1 < NC) {
            stage(k + 1);
            asm volatile("cp.async.commit_group;\n");
            asm volatile("cp.async.wait_group 1;\n" ::: "memory");
        } else {
            asm volatile("cp.async.wait_group 0;\n" ::: "memory");
        }
        __syncthreads();

        if (active) {
            const float* buf = sm + (k & 1) * BUFSZ;
            if (sh == 0)
                accum_chunk<0>(buf, xb, yo, acc);
            else
                accum_chunk<1>(buf, xb, yo, acc);
        }
        __syncthreads();
    }

    // ---- store 7x8 tile ----
    if (active) {
#pragma unroll
        for (int i = 0; i < 7; i++) {
            const int d = d0 + i;
            float* o = out + (((long)b * D_DIM + d) * H_DIM + h) * W_DIM + w0;
            float2 p0 = upk(acc[i * 4 + 0]);
            float2 p1 = upk(acc[i * 4 + 1]);
            float2 p2 = upk(acc[i * 4 + 2]);
            float2 p3 = upk(acc[i * 4 + 3]);
            *reinterpret_cast<float4*>(o) = make_float4(p0.x, p0.y, p1.x, p1.y);
            *reinterpret_cast<float4*>(o + 4) = make_float4(p2.x, p2.y, p3.x, p3.y);
        }
    }
}

extern "C" void kernel_launch(void* const* d_in, const int* in_sizes, int n_in,
                              void* d_out, int out_size) {
    const float* x = (const float*)d_in[0];
    const float* y = (const float*)d_in[1];
    float* out = (float*)d_out;

    cudaFuncSetAttribute(coex_cost_kernel,
                         cudaFuncAttributeMaxDynamicSharedMemorySize, SMEM_BYTES);

    coex_cost_kernel<<<B_DIM * H_DIM, NTHREADS, SMEM_BYTES>>>(x, y, out);
}

// round 4
// speedup vs baseline: 1.1973x; 1.1973x over previous
#include <cuda_runtime.h>

// CoExCostVolume: cost[b,d,h,w] = sum_c x[b,c,h,w] * y[b,c,h,w-d], zero for w<d.
// B=8, C=96, H=128, W=416, D=49.
//
// One CTA per (b,h) row. 4-buffer cp.async pipeline over 8 channel chunks of 12.
// Thread tile: 8 disparities x 8 widths (d0 multiple of 8 => uniform alignment
// phase => all smem offsets are immediates). x: +2/8 skew, conflict-free LDS.64.
// y: +1/8 skew, conflict-free scalar LDS. Packed fma.rn.f32x2 accumulation.

#define B_DIM 8
#define C_DIM 96
#define H_DIM 128
#define W_DIM 416
#define D_DIM 49
#define HW (H_DIM * W_DIM)

#define CC 12                 // channels per chunk
#define NC 8                  // chunks
#define NBUF 4
#define XSTRIDE 520           // >= sidxx(415)+1 = 518
#define YSTRIDE 524           // >= sidxy(463)+1 = 521
#define XSZ (CC * XSTRIDE)
#define YSZ (CC * YSTRIDE)
#define BUFSZ (XSZ + YSZ)
#define NTHREADS 448
#define SMEM_BYTES (NBUF * BUFSZ * 4)

typedef unsigned long long ull;

__device__ __forceinline__ int sidxy(int p) { return p + (p >> 3); }        // +1/8
__device__ __forceinline__ int sidxx(int p) { return p + ((p >> 3) << 1); } // +2/8

__device__ __forceinline__ void cp8(float* dst_smem, const float* src) {
    unsigned s = (unsigned)__cvta_generic_to_shared(dst_smem);
    asm volatile("cp.async.ca.shared.global [%0], [%1], 8;\n" ::"r"(s), "l"(src));
}
__device__ __forceinline__ void cp4(float* dst_smem, const float* src) {
    unsigned s = (unsigned)__cvta_generic_to_shared(dst_smem);
    asm volatile("cp.async.ca.shared.global [%0], [%1], 4;\n" ::"r"(s), "l"(src));
}
__device__ __forceinline__ ull pk(float lo, float hi) {
    ull r; asm("mov.b64 %0, {%1, %2};" : "=l"(r) : "f"(lo), "f"(hi)); return r;
}
__device__ __forceinline__ void fma2(ull& d, ull a, ull b) {
    asm("fma.rn.f32x2 %0, %1, %2, %0;" : "+l"(d) : "l"(a), "l"(b));
}
__device__ __forceinline__ float2 upk(ull p) {
    float2 v; asm("mov.b64 {%0, %1}, %2;" : "=f"(v.x), "=f"(v.y) : "l"(p)); return v;
}

// y offset immediates: window base has phase 1 (base = Q + 1, Q multiple of 8)
#define OY(t) (((t) + 1) + (((t) + 1) >> 3))
// d48 path: base phase 0
#define OY0(t) ((t) + ((t) >> 3))

__global__ void __launch_bounds__(NTHREADS, 1)
coex_cost_kernel(const float* __restrict__ x,
                 const float* __restrict__ y,
                 float* __restrict__ out) {
    extern __shared__ float sm[];

    const int bid = blockIdx.x;
    const int b = bid >> 7;
    const int h = bid & 127;
    const int tid = threadIdx.x;

    const int dth = tid / 52;        // 0..8 ; 0..5 main, 6 = d48, >=7 staging-only
    const int wth = tid - dth * 52;  // 0..51
    const bool main_t = (dth < 6);
    const bool d48_t = (dth == 6);
    const int d0 = dth * 8;          // 0,8,...,40 for main
    const int w0 = wth * 8;

    // ---- zero y left-pad once (all buffers): skewed coords [0, 54) ----
    for (int i = tid; i < NBUF * CC * 54; i += NTHREADS) {
        int br = i / 54;
        int p = i - br * 54;
        int buf = br / CC;
        int c = br - buf * CC;
        sm[buf * BUFSZ + XSZ + c * YSTRIDE + p] = 0.0f;
    }

    // ---- per-thread smem base offsets (immediate-relative) ----
    const int xb = sidxx(w0);
    // main: window base (padded coords) = w0 + 41 - d0 ; phase 1, Q = base-1
    const int yb_main = sidxy(w0 + 40 - d0) + 1;  // sidxy(Q)+? base addr of phase-1 window:
    // NOTE: loads use yq + OY(t) where yq = sidxy(Q), Q = w0+40-d0 (mult of 8)
    const int yq = sidxy(w0 + 40 - (main_t ? d0 : 0));
    (void)yb_main;
    // d48: base coord w0 (phase 0)
    const int yq48 = sidxy(w0);

    ull acc[32];
#pragma unroll
    for (int i = 0; i < 32; i++) acc[i] = 0ull;
    ull acc48[4];
#pragma unroll
    for (int i = 0; i < 4; i++) acc48[i] = 0ull;

    const long gbase = ((long)(b * C_DIM) * H_DIM + h) * W_DIM;

    // ---- staging: x as 8B, y as 4B cp.async ----
    auto stage = [&](int k) {
        const float* xg = x + gbase + (long)k * CC * HW;
        const float* yg = y + gbase + (long)k * CC * HW;
        float* xs = sm + (k & (NBUF - 1)) * BUFSZ;
        float* ys = xs + XSZ;
        // x: CC*208 = 2496 float2
#pragma unroll
        for (int it = 0; it < 6; it++) {
            int idx = tid + it * NTHREADS;
            if (idx < CC * 208) {
                int c = idx / 208;
                int w = (idx - c * 208) * 2;
                cp8(xs + c * XSTRIDE + sidxx(w), xg + (long)c * HW + w);
            }
        }
        // y: CC*416 = 4992 floats
#pragma unroll
        for (int it = 0; it < 12; it++) {
            int idx = tid + it * NTHREADS;
            if (idx < CC * W_DIM) {
                int c = idx / W_DIM;
                int w = idx - c * W_DIM;
                cp4(ys + c * YSTRIDE + sidxy(48 + w), yg + (long)c * HW + w);
            }
        }
    };

    stage(0); asm volatile("cp.async.commit_group;\n");
    stage(1); asm volatile("cp.async.commit_group;\n");
    stage(2); asm volatile("cp.async.commit_group;\n");

#pragma unroll 1
    for (int k = 0; k < NC; k++) {
        if (k < 6)      asm volatile("cp.async.wait_group 2;\n" ::: "memory");
        else if (k == 6) asm volatile("cp.async.wait_group 1;\n" ::: "memory");
        else             asm volatile("cp.async.wait_group 0;\n" ::: "memory");
        __syncthreads();

        if (k + 3 < NC) {
            stage(k + 3);
            asm volatile("cp.async.commit_group;\n");
        }

        const float* buf = sm + (k & (NBUF - 1)) * BUFSZ;
        if (main_t) {
            const float* xr = buf + xb;
            const float* yr = buf + XSZ + yq;
#pragma unroll 2
            for (int c = 0; c < CC; c++) {
                float2 xp[4];
#pragma unroll
                for (int j = 0; j < 4; j++)
                    xp[j] = *reinterpret_cast<const float2*>(xr + 2 * j);
                float yv[15];
#pragma unroll
                for (int t = 0; t < 15; t++) yv[t] = yr[OY(t)];

                ull px[4];
#pragma unroll
                for (int j = 0; j < 4; j++) px[j] = pk(xp[j].x, xp[j].y);
                ull py[14];
#pragma unroll
                for (int t = 0; t < 14; t++) py[t] = pk(yv[t], yv[t + 1]);

#pragma unroll
                for (int i = 0; i < 8; i++)
#pragma unroll
                    for (int j = 0; j < 4; j++)
                        fma2(acc[i * 4 + j], px[j], py[2 * j + 7 - i]);

                xr += XSTRIDE; yr += YSTRIDE;
            }
        } else if (d48_t) {
            const float* xr = buf + xb;
            const float* yr = buf + XSZ + yq48;
#pragma unroll 4
            for (int c = 0; c < CC; c++) {
                float2 xp[4];
#pragma unroll
                for (int j = 0; j < 4; j++)
                    xp[j] = *reinterpret_cast<const float2*>(xr + 2 * j);
                float yv[8];
#pragma unroll
                for (int t = 0; t < 8; t++) yv[t] = yr[OY0(t)];
#pragma unroll
                for (int j = 0; j < 4; j++) {
                    ull px = pk(xp[j].x, xp[j].y);
                    ull py = pk(yv[2 * j], yv[2 * j + 1]);
                    fma2(acc48[j], px, py);
                }
                xr += XSTRIDE; yr += YSTRIDE;
            }
        }
    }

    // ---- stores ----
    if (main_t) {
#pragma unroll
        for (int i = 0; i < 8; i++) {
            const int d = d0 + i;
            float* o = out + (((long)b * D_DIM + d) * H_DIM + h) * W_DIM + w0;
            float2 p0 = upk(acc[i * 4 + 0]);
            float2 p1 = upk(acc[i * 4 + 1]);
            float2 p2 = upk(acc[i * 4 + 2]);
            float2 p3 = upk(acc[i * 4 + 3]);
            *reinterpret_cast<float4*>(o) = make_float4(p0.x, p0.y, p1.x, p1.y);
            *reinterpret_cast<float4*>(o + 4) = make_float4(p2.x, p2.y, p3.x, p3.y);
        }
    } else if (d48_t) {
        float* o = out + (((long)b * D_DIM + 48) * H_DIM + h) * W_DIM + w0;
        float2 p0 = upk(acc48[0]);
        float2 p1 = upk(acc48[1]);
        float2 p2 = upk(acc48[2]);
        float2 p3 = upk(acc48[3]);
        *reinterpret_cast<float4*>(o) = make_float4(p0.x, p0.y, p1.x, p1.y);
        *reinterpret_cast<float4*>(o + 4) = make_float4(p2.x, p2.y, p3.x, p3.y);
    }
}

extern "C" void kernel_launch(void* const* d_in, const int* in_sizes, int n_in,
                              void* d_out, int out_size) {
    const float* x = (const float*)d_in[0];
    const float* y = (const float*)d_in[1];
    float* out = (float*)d_out;

    cudaFuncSetAttribute(coex_cost_kernel,
                         cudaFuncAttributeMaxDynamicSharedMemorySize, SMEM_BYTES);

    coex_cost_kernel<<<B_DIM * H_DIM, NTHREADS, SMEM_BYTES>>>(x, y, out);
}